// round 2
// baseline (speedup 1.0000x reference)
#include <cuda_runtime.h>

// ---------------------------------------------------------------------------
// SpikingSelfAttention  (T=4, B=16, N=1024, D=512, H=8)
//   pre_q/k/v = x @ W{q,k,v}^T          (fp32 GEMM, FFMA2 path)
//   spikes via LIF recurrence (decay 0.9, thr 1.0, soft reset)
//   o = q_spike * cumsum_t(k_spike * v_spike)      (elementwise; heads no-op)
//   out = o @ Wp^T + bp                 (fp32 GEMM, FFMA2 path)
// ---------------------------------------------------------------------------

namespace {
constexpr int    kT    = 4;
constexpr int    kM    = 16384;              // B*N
constexpr int    kD    = 512;
constexpr int    kRows = kT * kM;            // 65536
constexpr size_t kMD   = (size_t)kM * kD;    // 8388608
constexpr size_t kTMD  = (size_t)kRows * kD; // 33554432
}

// Scratch (allocation-free rule: __device__ global). Slot 0 (q pre-act) is
// overwritten in place by lif_fuse with q_spike*context, then consumed by
// gemm_proj. 402 MB total.
__device__ float g_pre[3 * kTMD];

// ------------------------------ f32x2 helpers ------------------------------
__device__ __forceinline__ unsigned long long dup_f32x2(float v) {
    unsigned long long r;
    asm("mov.b64 %0, {%1, %2};" : "=l"(r) : "f"(v), "f"(v));
    return r;
}
#define FMA2(c, a, b) asm("fma.rn.f32x2 %0, %1, %2, %0;" : "+l"(c) : "l"(a), "l"(b))

// ------------------------------ SGEMM core ---------------------------------
// C[r][j] = sum_d A[r][d] * W[j][d]  (+ bias[j])
// A row-major lda=512, W row-major (512x512), C row-major ldc=512.
// Block tile 128x128, K-chunk 16, 256 threads, 8x8 per thread (4+4 split
// fragments for conflict-free LDS), fp32x2 packed FMA inner loop.
template <bool BIAS>
__device__ __forceinline__ void gemm_core(const float* __restrict__ A,
                                          const float* __restrict__ W,
                                          float* __restrict__ C,
                                          const float* __restrict__ bias,
                                          int jbase) {
    __shared__ __align__(16) float As[16][132];
    __shared__ __align__(16) float Bs[16][132];

    const int tid   = threadIdx.x;
    const int ybase = blockIdx.y * 128;

    // global->smem staging mapping: 64 rows per pass, 2 passes, float4 each
    const int lrow = tid >> 2;            // 0..63
    const int lcol = (tid & 3) << 2;      // 0,4,8,12
    const float* Ag = A + (size_t)(ybase + lrow) * 512 + lcol;
    const float* Wg = W + (size_t)(jbase + lrow) * 512 + lcol;

    // compute mapping: 16x16 thread grid, fragments split 4+4 across halves
    const int tr4 = (tid & 15) * 4;       // m fragment base (and +64)
    const int tc4 = (tid >> 4) * 4;       // n fragment base (and +64)

    unsigned long long acc[8][4];
#pragma unroll
    for (int i = 0; i < 8; i++)
#pragma unroll
        for (int j = 0; j < 4; j++) acc[i][j] = 0ull;

    float4 pa0, pa1, pb0, pb1;

    auto load_chunk = [&](int k0) {
        pa0 = *(const float4*)(Ag + k0);
        pa1 = *(const float4*)(Ag + 64 * 512 + k0);
        pb0 = *(const float4*)(Wg + k0);
        pb1 = *(const float4*)(Wg + 64 * 512 + k0);
    };
    auto stage = [&]() {
        As[lcol + 0][lrow] = pa0.x; As[lcol + 1][lrow] = pa0.y;
        As[lcol + 2][lrow] = pa0.z; As[lcol + 3][lrow] = pa0.w;
        As[lcol + 0][lrow + 64] = pa1.x; As[lcol + 1][lrow + 64] = pa1.y;
        As[lcol + 2][lrow + 64] = pa1.z; As[lcol + 3][lrow + 64] = pa1.w;
        Bs[lcol + 0][lrow] = pb0.x; Bs[lcol + 1][lrow] = pb0.y;
        Bs[lcol + 2][lrow] = pb0.z; Bs[lcol + 3][lrow] = pb0.w;
        Bs[lcol + 0][lrow + 64] = pb1.x; Bs[lcol + 1][lrow + 64] = pb1.y;
        Bs[lcol + 2][lrow + 64] = pb1.z; Bs[lcol + 3][lrow + 64] = pb1.w;
    };
    auto compute = [&]() {
#pragma unroll
        for (int k = 0; k < 16; k++) {
            float4 a0 = *(const float4*)&As[k][tr4];
            float4 a1 = *(const float4*)&As[k][64 + tr4];
            ulonglong2 bq0 = *(const ulonglong2*)&Bs[k][tc4];
            ulonglong2 bq1 = *(const ulonglong2*)&Bs[k][64 + tc4];
            const unsigned long long bb0 = bq0.x, bb1 = bq0.y;
            const unsigned long long bb2 = bq1.x, bb3 = bq1.y;
            float am[8] = {a0.x, a0.y, a0.z, a0.w, a1.x, a1.y, a1.z, a1.w};
#pragma unroll
            for (int i = 0; i < 8; i++) {
                unsigned long long ad = dup_f32x2(am[i]);
                FMA2(acc[i][0], ad, bb0);
                FMA2(acc[i][1], ad, bb1);
                FMA2(acc[i][2], ad, bb2);
                FMA2(acc[i][3], ad, bb3);
            }
        }
    };

    load_chunk(0);
    stage();
    __syncthreads();

    for (int k0 = 16; k0 < 512; k0 += 16) {
        load_chunk(k0);        // global loads in flight during compute
        compute();
        __syncthreads();
        stage();
        __syncthreads();
    }
    compute();

    // epilogue
#pragma unroll
    for (int i = 0; i < 8; i++) {
        const int m = ybase + ((i < 4) ? (tr4 + i) : (64 + tr4 + i - 4));
        float* Crow = C + (size_t)m * 512 + jbase;
#pragma unroll
        for (int j = 0; j < 4; j++) {
            const int n = (j < 2) ? (tc4 + 2 * j) : (64 + tc4 + 2 * (j - 2));
            float2 v = *(float2*)&acc[i][j];
            if (BIAS) {
                v.x += bias[jbase + n];
                v.y += bias[jbase + n + 1];
            }
            *(float2*)(Crow + n) = v;
        }
    }
}

// grid (12, 512): x = 3 weights x 4 column tiles (x-fastest => A-tile L2 reuse
// across all 12 consumers of the same row block)
__global__ __launch_bounds__(256, 2) void gemm_qkv(const float* __restrict__ x,
                                                   const float* __restrict__ Wq,
                                                   const float* __restrict__ Wk,
                                                   const float* __restrict__ Wv) {
    const int wsel = blockIdx.x >> 2;
    const float* W = (wsel == 0) ? Wq : (wsel == 1) ? Wk : Wv;
    float* C = g_pre + (size_t)wsel * kTMD;
    gemm_core<false>(x, W, C, nullptr, (blockIdx.x & 3) * 128);
}

// grid (4, 512): reads q_spike*context from g_pre slot 0 (written by lif_fuse)
__global__ __launch_bounds__(256, 2) void gemm_proj(const float* __restrict__ Wp,
                                                    const float* __restrict__ bp,
                                                    float* __restrict__ out) {
    gemm_core<true>(g_pre, Wp, out, bp, blockIdx.x * 128);
}

// LIF recurrence + kv cumsum + q*context, fused elementwise over (M*D),
// time loop in registers (T=4). Writes result in place into the q slot.
__global__ void lif_fuse() {
    const size_t idx = (size_t)blockIdx.x * blockDim.x + threadIdx.x;
    float mq = 0.f, mk = 0.f, mv = 0.f, ctx = 0.f;
#pragma unroll
    for (int t = 0; t < kT; t++) {
        const size_t o = (size_t)t * kMD + idx;
        mq = mq * 0.9f + g_pre[o];
        mk = mk * 0.9f + g_pre[kTMD + o];
        mv = mv * 0.9f + g_pre[2 * kTMD + o];
        const float sq = (mq >= 1.0f) ? 1.f : 0.f;
        const float sk = (mk >= 1.0f) ? 1.f : 0.f;
        const float sv = (mv >= 1.0f) ? 1.f : 0.f;
        mq -= sq;
        mk -= sk;
        mv -= sv;
        ctx += sk * sv;
        g_pre[o] = sq * ctx;   // in-place: q pre-act no longer needed
    }
}

extern "C" void kernel_launch(void* const* d_in, const int* in_sizes, int n_in,
                              void* d_out, int out_size) {
    const float* x  = (const float*)d_in[0];
    const float* Wq = (const float*)d_in[1];
    const float* Wk = (const float*)d_in[2];
    const float* Wv = (const float*)d_in[3];
    const float* Wp = (const float*)d_in[4];
    const float* bp = (const float*)d_in[5];
    float* out = (float*)d_out;

    dim3 g1(12, kRows / 128, 1);
    gemm_qkv<<<g1, 256>>>(x, Wq, Wk, Wv);

    lif_fuse<<<(int)(kMD / 256), 256>>>();

    dim3 g2(4, kRows / 128, 1);
    gemm_proj<<<g2, 256>>>(Wp, bp, out);
}